// round 2
// baseline (speedup 1.0000x reference)
#include <cuda_runtime.h>
#include <cstdint>

#define T_TOK 4096
#define DM    1024
#define DFF   4096
#define KSEL  256
#define DH    64
#define DH2   32
#define DR    128

typedef unsigned long long ull;

// ---------------- scratch (static device globals; no runtime allocation) ----
__device__ float g_xn[(size_t)T_TOK * DM];
__device__ float g_h[(size_t)T_TOK * DM];
__device__ float g_scores[(size_t)T_TOK * DFF];
__device__ float g_z[(size_t)T_TOK * DFF];
__device__ float g_asel[(size_t)T_TOK * KSEL];
__device__ float g_man[(size_t)T_TOK * KSEL];
__device__ int   g_idx[(size_t)T_TOK * KSEL];
__device__ float g_w2t[(size_t)DFF * DM];

// ---------------- helpers ---------------------------------------------------
__device__ __forceinline__ float gelu_f(float x) {
    return 0.5f * x * (1.0f + erff(x * 0.7071067811865475f));
}
__device__ __forceinline__ ull pack2(float lo, float hi) {
    ull r; asm("mov.b64 %0, {%1,%2};" : "=l"(r) : "f"(lo), "f"(hi)); return r;
}
__device__ __forceinline__ void unpack2(ull v, float &lo, float &hi) {
    asm("mov.b64 {%0,%1}, %2;" : "=f"(lo), "=f"(hi) : "l"(v));
}
__device__ __forceinline__ ull ffma2(ull a, ull b, ull c) {
    ull d; asm("fma.rn.f32x2 %0, %1, %2, %3;" : "=l"(d) : "l"(a), "l"(b), "l"(c));
    return d;
}

// ---------------- layernorm of x -> g_xn ------------------------------------
__global__ void __launch_bounds__(256) k_ln(const float* __restrict__ x,
                                            const float* __restrict__ w,
                                            const float* __restrict__ b) {
    __shared__ float red[8];
    int t = blockIdx.x, tid = threadIdx.x;
    const float4* row = (const float4*)(x + (size_t)t * DM);
    float4 v = row[tid];
    float s = v.x + v.y + v.z + v.w;
    #pragma unroll
    for (int o = 16; o; o >>= 1) s += __shfl_down_sync(0xffffffffu, s, o);
    if ((tid & 31) == 0) red[tid >> 5] = s;
    __syncthreads();
    float tot = 0.f;
    #pragma unroll
    for (int i = 0; i < 8; i++) tot += red[i];
    float mu = tot * (1.0f / DM);
    __syncthreads();
    float dx = v.x - mu, dy = v.y - mu, dz = v.z - mu, dw = v.w - mu;
    float q = dx * dx + dy * dy + dz * dz + dw * dw;
    #pragma unroll
    for (int o = 16; o; o >>= 1) q += __shfl_down_sync(0xffffffffu, q, o);
    if ((tid & 31) == 0) red[tid >> 5] = q;
    __syncthreads();
    float vt = 0.f;
    #pragma unroll
    for (int i = 0; i < 8; i++) vt += red[i];
    float inv = rsqrtf(vt * (1.0f / DM) + 1e-5f);
    float4 wv = ((const float4*)w)[tid];
    float4 bv = ((const float4*)b)[tid];
    float4 o;
    o.x = dx * inv * wv.x + bv.x;
    o.y = dy * inv * wv.y + bv.y;
    o.z = dz * inv * wv.z + bv.z;
    o.w = dw * inv * wv.w + bv.w;
    ((float4*)(g_xn + (size_t)t * DM))[tid] = o;
}

// ---------------- fp32 GEMM core: C[m,n] = sum_k A[m,k]*B[n,k] --------------
// K fixed at 1024. 128x128 block tile, 256 threads, 8x8 per thread, FFMA2.
__device__ __forceinline__ void gemm_core(const float* __restrict__ A,
                                          const float* __restrict__ B,
                                          float* __restrict__ C,
                                          int N, bool do_gelu) {
    const int K = 1024;
    __shared__ float As[8][128];
    __shared__ float Bs[8][128];
    int tid = threadIdx.x;
    int m0 = blockIdx.y * 128, n0 = blockIdx.x * 128;
    int lr = tid >> 1;
    int lc = (tid & 1) * 4;
    const float* Ag = A + (size_t)(m0 + lr) * K + lc;
    const float* Bg = B + (size_t)(n0 + lr) * K + lc;
    int tx = tid & 15, ty = tid >> 4;
    int mo = ty * 8, no = tx * 8;

    ull acc[32];
    #pragma unroll
    for (int i = 0; i < 32; i++) acc[i] = 0ull;  // bit pattern = {+0.f,+0.f}

    float4 a4 = *(const float4*)Ag;
    float4 b4 = *(const float4*)Bg;

    #pragma unroll 1
    for (int kt = 0; kt < K / 8; kt++) {
        As[lc + 0][lr] = a4.x; As[lc + 1][lr] = a4.y;
        As[lc + 2][lr] = a4.z; As[lc + 3][lr] = a4.w;
        Bs[lc + 0][lr] = b4.x; Bs[lc + 1][lr] = b4.y;
        Bs[lc + 2][lr] = b4.z; Bs[lc + 3][lr] = b4.w;
        __syncthreads();
        if (kt + 1 < K / 8) {
            a4 = *(const float4*)(Ag + (kt + 1) * 8);
            b4 = *(const float4*)(Bg + (kt + 1) * 8);
        }
        #pragma unroll
        for (int k = 0; k < 8; k++) {
            float4 aA = *(const float4*)&As[k][mo];
            float4 aB = *(const float4*)&As[k][mo + 4];
            const ull* bp = (const ull*)&Bs[k][no];
            ull b0 = bp[0], b1 = bp[1], b2 = bp[2], b3 = bp[3];
            float am[8] = {aA.x, aA.y, aA.z, aA.w, aB.x, aB.y, aB.z, aB.w};
            #pragma unroll
            for (int i = 0; i < 8; i++) {
                ull ap = pack2(am[i], am[i]);
                acc[i * 4 + 0] = ffma2(ap, b0, acc[i * 4 + 0]);
                acc[i * 4 + 1] = ffma2(ap, b1, acc[i * 4 + 1]);
                acc[i * 4 + 2] = ffma2(ap, b2, acc[i * 4 + 2]);
                acc[i * 4 + 3] = ffma2(ap, b3, acc[i * 4 + 3]);
            }
        }
        __syncthreads();
    }
    #pragma unroll
    for (int i = 0; i < 8; i++) {
        float* crow = C + (size_t)(m0 + mo + i) * N + n0 + no;
        #pragma unroll
        for (int p = 0; p < 4; p++) {
            float lo, hi;
            unpack2(acc[i * 4 + p], lo, hi);
            if (do_gelu) { lo = gelu_f(lo); hi = gelu_f(hi); }
            crow[2 * p]     = lo;
            crow[2 * p + 1] = hi;
        }
    }
}

__global__ void __launch_bounds__(256, 2) k_gemm_router1(const float* __restrict__ Wr1) {
    gemm_core(g_xn, Wr1, g_h, DM, true);
}
__global__ void __launch_bounds__(256, 2) k_gemm_scores(const float* __restrict__ Wr2) {
    gemm_core(g_h, Wr2, g_scores, DFF, false);
}
__global__ void __launch_bounds__(256, 2) k_gemm_z(const float* __restrict__ x,
                                                   const float* __restrict__ W1) {
    gemm_core(x, W1, g_z, DFF, false);
}

// ---------------- transpose W2 [DM,DFF] -> g_w2t [DFF,DM] -------------------
__global__ void k_transpose(const float* __restrict__ W2) {
    __shared__ float tile[32][33];
    int x = blockIdx.x * 32 + threadIdx.x;   // DFF index
    int y0 = blockIdx.y * 32;                // DM index
    for (int j = threadIdx.y; j < 32; j += 8)
        tile[j][threadIdx.x] = W2[(size_t)(y0 + j) * DFF + x];
    __syncthreads();
    int ox  = blockIdx.y * 32 + threadIdx.x; // DM index
    int oy0 = blockIdx.x * 32;               // DFF index
    for (int j = threadIdx.y; j < 32; j += 8)
        g_w2t[(size_t)(oy0 + j) * DM + ox] = tile[threadIdx.x][j];
}

// ---------------- exact top-256 radix select per token ----------------------
__global__ void __launch_bounds__(256) k_topk() {
    __shared__ unsigned int keys[4096];
    __shared__ int hist[256];
    __shared__ int scan[256];
    __shared__ int sh_bin, sh_rem, sh_cnt, sh_eqbase;
    __shared__ int sel[256];
    __shared__ int warp_tot[8];

    int t = blockIdx.x, tid = threadIdx.x;
    const float* srow = g_scores + (size_t)t * DFF;

    for (int i = tid; i < 4096; i += 256) {
        unsigned int u = __float_as_uint(srow[i]);
        u = (u & 0x80000000u) ? ~u : (u | 0x80000000u);
        keys[i] = u;
    }
    unsigned int prefix = 0, pmask = 0;
    int remaining = KSEL;
    for (int pass = 0; pass < 4; pass++) {
        int shift = 24 - 8 * pass;
        hist[tid] = 0;
        __syncthreads();
        for (int i = tid; i < 4096; i += 256) {
            unsigned int k = keys[i];
            if ((k & pmask) == prefix) atomicAdd(&hist[(k >> shift) & 0xFF], 1);
        }
        __syncthreads();
        // suffix (from high bin) inclusive scan: scan[r] over reversed bins
        scan[tid] = hist[255 - tid];
        __syncthreads();
        #pragma unroll
        for (int off = 1; off < 256; off <<= 1) {
            int v = scan[tid];
            int add = (tid >= off) ? scan[tid - off] : 0;
            __syncthreads();
            scan[tid] = v + add;
            __syncthreads();
        }
        {
            int b = 255 - tid;
            int incl = scan[tid];            // count of keys with digit >= b
            int h = hist[b];
            int excl = incl - h;             // count with digit > b
            if (incl >= remaining && excl < remaining) {
                sh_bin = b;
                sh_rem = remaining - excl;
            }
        }
        __syncthreads();
        prefix |= ((unsigned)sh_bin) << shift;
        pmask  |= 0xFFu << shift;
        remaining = sh_rem;
        __syncthreads();
    }
    unsigned int thresh = prefix;

    // compaction of keys strictly greater than threshold (order irrelevant)
    if (tid == 0) sh_cnt = 0;
    __syncthreads();
    for (int i = tid; i < 4096; i += 256) {
        if (keys[i] > thresh) {
            int p = atomicAdd(&sh_cnt, 1);
            sel[p] = i;
        }
    }
    __syncthreads();
    int n_gt = sh_cnt;
    int n_eq = KSEL - n_gt;  // ties: take lowest indices (matches lax.top_k)

    if (tid == 0) sh_eqbase = 0;
    __syncthreads();
    int lane = tid & 31, w = tid >> 5;
    for (int c = 0; c < 16; c++) {
        if (sh_eqbase >= n_eq) break;
        int i = c * 256 + tid;
        bool p = (keys[i] == thresh);
        unsigned int ball = __ballot_sync(0xffffffffu, p);
        int rin = __popc(ball & ((1u << lane) - 1));
        if (lane == 0) warp_tot[w] = __popc(ball);
        __syncthreads();
        int pre = 0;
        for (int ww = 0; ww < w; ww++) pre += warp_tot[ww];
        int grank = sh_eqbase + pre + rin;
        if (p && grank < n_eq) sel[n_gt + grank] = i;
        __syncthreads();
        if (tid == 0) {
            int tot = 0;
            for (int ww = 0; ww < 8; ww++) tot += warp_tot[ww];
            sh_eqbase += tot;
        }
        __syncthreads();
    }

    int i = sel[tid];
    g_idx[(size_t)t * KSEL + tid] = i;
    float z = g_z[(size_t)t * DFF + i];
    g_asel[(size_t)t * KSEL + tid] = gelu_f(z);
}

// ---------------- fused DeepSets per token ----------------------------------
__global__ void __launch_bounds__(256) k_deepsets(
    const float* __restrict__ phi1_w, const float* __restrict__ phi1_b,
    const float* __restrict__ ln1w,   const float* __restrict__ ln1b,
    const float* __restrict__ phi2_w, const float* __restrict__ phi2_b,
    const float* __restrict__ ln2w,   const float* __restrict__ ln2b,
    const float* __restrict__ rho1_w, const float* __restrict__ rho1_b,
    const float* __restrict__ rho2_w, const float* __restrict__ rho2_b) {
    __shared__ float s_p1w[DH2], s_p1b[DH2], s_l1w[DH2], s_l1b[DH2];
    __shared__ float s_p2w[DH * DH2], s_p2b[DH], s_l2w[DH], s_l2b[DH];
    __shared__ float s_r1w[DR * DH], s_r1b[DR], s_r2w[DR];
    __shared__ float s_wsum[8][DH];
    __shared__ float s_ctx[DH];

    int t = blockIdx.x, tid = threadIdx.x;
    if (tid < DH2) {
        s_p1w[tid] = phi1_w[tid]; s_p1b[tid] = phi1_b[tid];
        s_l1w[tid] = ln1w[tid];   s_l1b[tid] = ln1b[tid];
    }
    if (tid < DH) {
        s_p2b[tid] = phi2_b[tid]; s_l2w[tid] = ln2w[tid]; s_l2b[tid] = ln2b[tid];
    }
    if (tid < DR) { s_r1b[tid] = rho1_b[tid]; s_r2w[tid] = rho2_w[tid]; }
    for (int i = tid; i < DH * DH2; i += 256) s_p2w[i] = phi2_w[i];
    for (int i = tid; i < DR * DH; i += 256) s_r1w[i] = rho1_w[i];
    float r2b = rho2_b[0];
    __syncthreads();

    float a = g_asel[(size_t)t * KSEL + tid];

    // phi1 + LN + gelu
    float e1[DH2];
    float mu = 0.f;
    #pragma unroll
    for (int j = 0; j < DH2; j++) { e1[j] = fmaf(a, s_p1w[j], s_p1b[j]); mu += e1[j]; }
    mu *= (1.0f / DH2);
    float var = 0.f;
    #pragma unroll
    for (int j = 0; j < DH2; j++) { float d = e1[j] - mu; var += d * d; }
    float inv = rsqrtf(var * (1.0f / DH2) + 1e-5f);
    #pragma unroll
    for (int j = 0; j < DH2; j++)
        e1[j] = gelu_f((e1[j] - mu) * inv * s_l1w[j] + s_l1b[j]);

    // phi2 + LN
    float e2[DH];
    #pragma unroll 4
    for (int h = 0; h < DH; h++) {
        float a0 = 0.f, a1 = 0.f, a2 = 0.f, a3 = 0.f;
        const float* wr = &s_p2w[h * DH2];
        #pragma unroll
        for (int j = 0; j < DH2; j += 4) {
            float4 w4 = *(const float4*)(wr + j);
            a0 = fmaf(e1[j + 0], w4.x, a0);
            a1 = fmaf(e1[j + 1], w4.y, a1);
            a2 = fmaf(e1[j + 2], w4.z, a2);
            a3 = fmaf(e1[j + 3], w4.w, a3);
        }
        e2[h] = ((a0 + a1) + (a2 + a3)) + s_p2b[h];
    }
    float mu2 = 0.f;
    #pragma unroll
    for (int h = 0; h < DH; h++) mu2 += e2[h];
    mu2 *= (1.0f / DH);
    float var2 = 0.f;
    #pragma unroll
    for (int h = 0; h < DH; h++) { float d = e2[h] - mu2; var2 += d * d; }
    float inv2 = rsqrtf(var2 * (1.0f / DH) + 1e-5f);
    #pragma unroll
    for (int h = 0; h < DH; h++)
        e2[h] = (e2[h] - mu2) * inv2 * s_l2w[h] + s_l2b[h];

    // ctx = mean over K (warp shuffle + smem tree)
    int lane = tid & 31, w = tid >> 5;
    #pragma unroll
    for (int h = 0; h < DH; h++) {
        float v = e2[h];
        v += __shfl_down_sync(0xffffffffu, v, 16);
        v += __shfl_down_sync(0xffffffffu, v, 8);
        v += __shfl_down_sync(0xffffffffu, v, 4);
        v += __shfl_down_sync(0xffffffffu, v, 2);
        v += __shfl_down_sync(0xffffffffu, v, 1);
        if (lane == 0) s_wsum[w][h] = v;
    }
    __syncthreads();
    if (tid < DH) {
        float s = 0.f;
        #pragma unroll
        for (int ww = 0; ww < 8; ww++) s += s_wsum[ww][tid];
        s_ctx[tid] = s * (1.0f / KSEL);
    }
    __syncthreads();
    #pragma unroll
    for (int h = 0; h < DH; h++) e2[h] += s_ctx[h];  // c = e + ctx

    // rho1 -> gelu -> rho2
    float man = r2b;
    #pragma unroll 2
    for (int m = 0; m < DR; m++) {
        float a0 = 0.f, a1 = 0.f, a2 = 0.f, a3 = 0.f;
        const float* wr = &s_r1w[m * DH];
        #pragma unroll
        for (int h = 0; h < DH; h += 4) {
            float4 w4 = *(const float4*)(wr + h);
            a0 = fmaf(e2[h + 0], w4.x, a0);
            a1 = fmaf(e2[h + 1], w4.y, a1);
            a2 = fmaf(e2[h + 2], w4.z, a2);
            a3 = fmaf(e2[h + 3], w4.w, a3);
        }
        float acc = ((a0 + a1) + (a2 + a3)) + s_r1b[m];
        man = fmaf(s_r2w[m], gelu_f(acc), man);
    }
    g_man[(size_t)t * KSEL + tid] = man;
}

// ---------------- out[t,:] = sum_k man[t,k] * W2T[idx[t,k], :] --------------
__global__ void __launch_bounds__(256) k_out(float* __restrict__ out) {
    __shared__ float s_man[KSEL];
    __shared__ int s_idx[KSEL];
    int t = blockIdx.x, tid = threadIdx.x;
    s_man[tid] = g_man[(size_t)t * KSEL + tid];
    s_idx[tid] = g_idx[(size_t)t * KSEL + tid];
    __syncthreads();
    float4 acc = make_float4(0.f, 0.f, 0.f, 0.f);
    #pragma unroll 8
    for (int k = 0; k < KSEL; k++) {
        float m = s_man[k];
        float4 wv = ((const float4*)(g_w2t + (size_t)s_idx[k] * DM))[tid];
        acc.x = fmaf(m, wv.x, acc.x);
        acc.y = fmaf(m, wv.y, acc.y);
        acc.z = fmaf(m, wv.z, acc.z);
        acc.w = fmaf(m, wv.w, acc.w);
    }
    ((float4*)(out + (size_t)t * DM))[tid] = acc;
}

// ---------------- launch ----------------------------------------------------
extern "C" void kernel_launch(void* const* d_in, const int* in_sizes, int n_in,
                              void* d_out, int out_size) {
    const float* x      = (const float*)d_in[0];
    const float* W1     = (const float*)d_in[1];
    const float* W2     = (const float*)d_in[2];
    const float* Wr1    = (const float*)d_in[3];
    const float* Wr2    = (const float*)d_in[4];
    const float* ln_w   = (const float*)d_in[5];
    const float* ln_b   = (const float*)d_in[6];
    const float* phi1_w = (const float*)d_in[7];
    const float* phi1_b = (const float*)d_in[8];
    const float* pl1w   = (const float*)d_in[9];
    const float* pl1b   = (const float*)d_in[10];
    const float* phi2_w = (const float*)d_in[11];
    const float* phi2_b = (const float*)d_in[12];
    const float* pl2w   = (const float*)d_in[13];
    const float* pl2b   = (const float*)d_in[14];
    const float* rho1_w = (const float*)d_in[15];
    const float* rho1_b = (const float*)d_in[16];
    const float* rho2_w = (const float*)d_in[17];
    const float* rho2_b = (const float*)d_in[18];
    float* out = (float*)d_out;

    k_ln<<<T_TOK, 256>>>(x, ln_w, ln_b);
    k_gemm_router1<<<dim3(DM / 128, T_TOK / 128), 256>>>(Wr1);
    k_gemm_scores<<<dim3(DFF / 128, T_TOK / 128), 256>>>(Wr2);
    k_gemm_z<<<dim3(DFF / 128, T_TOK / 128), 256>>>(x, W1);
    k_transpose<<<dim3(DFF / 32, DM / 32), dim3(32, 8)>>>(W2);
    k_topk<<<T_TOK, 256>>>();
    k_deepsets<<<T_TOK, 256>>>(phi1_w, phi1_b, pl1w, pl1b,
                               phi2_w, phi2_b, pl2w, pl2b,
                               rho1_w, rho1_b, rho2_w, rho2_b);
    k_out<<<T_TOK, 256>>>(out);
}

// round 5
// speedup vs baseline: 1.2487x; 1.2487x over previous
#include <cuda_runtime.h>
#include <cuda_bf16.h>
#include <cstdint>

#define T_TOK 4096
#define DM    1024
#define DFF   4096
#define KSEL  256
#define DH    64
#define DH2   32
#define DR    128
#define NCHUNK 16
#define TILEB  16384

typedef unsigned long long ull;

// ---------------- scratch (static device globals) ---------------------------
__device__ float g_xn[(size_t)T_TOK * DM];
__device__ float g_h[(size_t)T_TOK * DM];
__device__ float g_scores[(size_t)T_TOK * DFF];
__device__ float g_z[(size_t)T_TOK * DFF];
__device__ float g_asel[(size_t)T_TOK * KSEL];
__device__ float g_man[(size_t)T_TOK * KSEL];
__device__ int   g_idx[(size_t)T_TOK * KSEL];
__device__ float g_w2t[(size_t)DFF * DM];

// bf16 2-term split buffers for the z GEMM (blocked + SW128-swizzled tiles)
__device__ ull g_xt0[(size_t)T_TOK * DM / 4], g_xt1[(size_t)T_TOK * DM / 4];
__device__ ull g_w1t0[(size_t)DFF * DM / 4],  g_w1t1[(size_t)DFF * DM / 4];

// ---------------- helpers ---------------------------------------------------
__device__ __forceinline__ float gelu_f(float x) {
    return 0.5f * x * (1.0f + erff(x * 0.7071067811865475f));
}
__device__ __forceinline__ ull pack2(float lo, float hi) {
    ull r; asm("mov.b64 %0, {%1,%2};" : "=l"(r) : "f"(lo), "f"(hi)); return r;
}
__device__ __forceinline__ void unpack2(ull v, float &lo, float &hi) {
    asm("mov.b64 {%0,%1}, %2;" : "=f"(lo), "=f"(hi) : "l"(v));
}
__device__ __forceinline__ ull ffma2(ull a, ull b, ull c) {
    ull d; asm("fma.rn.f32x2 %0, %1, %2, %3;" : "=l"(d) : "l"(a), "l"(b), "l"(c));
    return d;
}
__device__ __forceinline__ uint32_t s2u(const void* p) {
    uint32_t a;
    asm("{ .reg .u64 t; cvta.to.shared.u64 t, %1; cvt.u32.u64 %0, t; }" : "=r"(a) : "l"(p));
    return a;
}
__device__ __forceinline__ void cp16(uint32_t d, const void* s) {
    asm volatile("cp.async.cg.shared.global [%0], [%1], 16;" :: "r"(d), "l"(s) : "memory");
}
__device__ __forceinline__ void cp_commit() {
    asm volatile("cp.async.commit_group;" ::: "memory");
}
template <int N>
__device__ __forceinline__ void cp_wait() {
    asm volatile("cp.async.wait_group %0;" :: "n"(N) : "memory");
}
__device__ __forceinline__ void ldsm4(uint32_t* r, uint32_t addr) {
    asm volatile("ldmatrix.sync.aligned.m8n8.x4.shared.b16 {%0,%1,%2,%3}, [%4];"
                 : "=r"(r[0]), "=r"(r[1]), "=r"(r[2]), "=r"(r[3]) : "r"(addr));
}
__device__ __forceinline__ void mma16816(float* d, const uint32_t* a, const uint32_t* b) {
    asm volatile(
        "mma.sync.aligned.m16n8k16.row.col.f32.bf16.bf16.f32 "
        "{%0,%1,%2,%3}, {%4,%5,%6,%7}, {%8,%9}, {%0,%1,%2,%3};"
        : "+f"(d[0]), "+f"(d[1]), "+f"(d[2]), "+f"(d[3])
        : "r"(a[0]), "r"(a[1]), "r"(a[2]), "r"(a[3]), "r"(b[0]), "r"(b[1]));
}

// ---------------- layernorm of x -> g_xn (verbatim R1) ----------------------
__global__ void __launch_bounds__(256) k_ln(const float* __restrict__ x,
                                            const float* __restrict__ w,
                                            const float* __restrict__ b) {
    __shared__ float red[8];
    int t = blockIdx.x, tid = threadIdx.x;
    const float4* row = (const float4*)(x + (size_t)t * DM);
    float4 v = row[tid];
    float s = v.x + v.y + v.z + v.w;
    #pragma unroll
    for (int o = 16; o; o >>= 1) s += __shfl_down_sync(0xffffffffu, s, o);
    if ((tid & 31) == 0) red[tid >> 5] = s;
    __syncthreads();
    float tot = 0.f;
    #pragma unroll
    for (int i = 0; i < 8; i++) tot += red[i];
    float mu = tot * (1.0f / DM);
    __syncthreads();
    float dx = v.x - mu, dy = v.y - mu, dz = v.z - mu, dw = v.w - mu;
    float q = dx * dx + dy * dy + dz * dz + dw * dw;
    #pragma unroll
    for (int o = 16; o; o >>= 1) q += __shfl_down_sync(0xffffffffu, q, o);
    if ((tid & 31) == 0) red[tid >> 5] = q;
    __syncthreads();
    float vt = 0.f;
    #pragma unroll
    for (int i = 0; i < 8; i++) vt += red[i];
    float inv = rsqrtf(vt * (1.0f / DM) + 1e-5f);
    float4 wv = ((const float4*)w)[tid];
    float4 bv = ((const float4*)b)[tid];
    float4 o;
    o.x = dx * inv * wv.x + bv.x;
    o.y = dy * inv * wv.y + bv.y;
    o.z = dz * inv * wv.z + bv.z;
    o.w = dw * inv * wv.w + bv.w;
    ((float4*)(g_xn + (size_t)t * DM))[tid] = o;
}

// ---------------- fp32 FFMA2 GEMM core (verbatim R1 — bit-exact) ------------
__device__ __forceinline__ void gemm_core(const float* __restrict__ A,
                                          const float* __restrict__ B,
                                          float* __restrict__ C,
                                          int N, bool do_gelu) {
    const int K = 1024;
    __shared__ float As[8][128];
    __shared__ float Bs[8][128];
    int tid = threadIdx.x;
    int m0 = blockIdx.y * 128, n0 = blockIdx.x * 128;
    int lr = tid >> 1;
    int lc = (tid & 1) * 4;
    const float* Ag = A + (size_t)(m0 + lr) * K + lc;
    const float* Bg = B + (size_t)(n0 + lr) * K + lc;
    int tx = tid & 15, ty = tid >> 4;
    int mo = ty * 8, no = tx * 8;

    ull acc[32];
    #pragma unroll
    for (int i = 0; i < 32; i++) acc[i] = 0ull;

    float4 a4 = *(const float4*)Ag;
    float4 b4 = *(const float4*)Bg;

    #pragma unroll 1
    for (int kt = 0; kt < K / 8; kt++) {
        As[lc + 0][lr] = a4.x; As[lc + 1][lr] = a4.y;
        As[lc + 2][lr] = a4.z; As[lc + 3][lr] = a4.w;
        Bs[lc + 0][lr] = b4.x; Bs[lc + 1][lr] = b4.y;
        Bs[lc + 2][lr] = b4.z; Bs[lc + 3][lr] = b4.w;
        __syncthreads();
        if (kt + 1 < K / 8) {
            a4 = *(const float4*)(Ag + (kt + 1) * 8);
            b4 = *(const float4*)(Bg + (kt + 1) * 8);
        }
        #pragma unroll
        for (int k = 0; k < 8; k++) {
            float4 aA = *(const float4*)&As[k][mo];
            float4 aB = *(const float4*)&As[k][mo + 4];
            const ull* bp = (const ull*)&Bs[k][no];
            ull b0 = bp[0], b1 = bp[1], b2 = bp[2], b3 = bp[3];
            float am[8] = {aA.x, aA.y, aA.z, aA.w, aB.x, aB.y, aB.z, aB.w};
            #pragma unroll
            for (int i = 0; i < 8; i++) {
                ull ap = pack2(am[i], am[i]);
                acc[i * 4 + 0] = ffma2(ap, b0, acc[i * 4 + 0]);
                acc[i * 4 + 1] = ffma2(ap, b1, acc[i * 4 + 1]);
                acc[i * 4 + 2] = ffma2(ap, b2, acc[i * 4 + 2]);
                acc[i * 4 + 3] = ffma2(ap, b3, acc[i * 4 + 3]);
            }
        }
        __syncthreads();
    }
    #pragma unroll
    for (int i = 0; i < 8; i++) {
        float* crow = C + (size_t)(m0 + mo + i) * N + n0 + no;
        #pragma unroll
        for (int p = 0; p < 4; p++) {
            float lo, hi;
            unpack2(acc[i * 4 + p], lo, hi);
            if (do_gelu) { lo = gelu_f(lo); hi = gelu_f(hi); }
            crow[2 * p]     = lo;
            crow[2 * p + 1] = hi;
        }
    }
}

__global__ void __launch_bounds__(256, 2) k_gemm_router1(const float* __restrict__ Wr1) {
    gemm_core(g_xn, Wr1, g_h, DM, true);
}
__global__ void __launch_bounds__(256, 2) k_gemm_scores(const float* __restrict__ Wr2) {
    gemm_core(g_h, Wr2, g_scores, DFF, false);
}

// ---------------- split fp32 -> 2 bf16 terms, blocked swizzled tiles --------
__device__ __forceinline__ void conv_body2(const float* __restrict__ src,
                                           char* __restrict__ d0,
                                           char* __restrict__ d1) {
    int r = blockIdx.x, tid = threadIdx.x;
    float4 v = ((const float4*)(src + (size_t)r * DM))[tid];
    int c0 = tid * 4;
    int kc = c0 >> 6, cl = c0 & 63;
    uint32_t off = (uint32_t)((r & 127) * 128 + cl * 2);
    off ^= (off >> 3) & 0x70;
    size_t base = ((size_t)((r >> 7) * NCHUNK + kc)) * TILEB + off;
    float f[4] = {v.x, v.y, v.z, v.w};
    unsigned short u0[4], u1[4];
    #pragma unroll
    for (int j = 0; j < 4; j++) {
        __nv_bfloat16 h0 = __float2bfloat16(f[j]);
        float r1 = f[j] - __bfloat162float(h0);
        u0[j] = __bfloat16_as_ushort(h0);
        u1[j] = __bfloat16_as_ushort(__float2bfloat16(r1));
    }
    ull p0 = (ull)u0[0] | ((ull)u0[1] << 16) | ((ull)u0[2] << 32) | ((ull)u0[3] << 48);
    ull p1 = (ull)u1[0] | ((ull)u1[1] << 16) | ((ull)u1[2] << 32) | ((ull)u1[3] << 48);
    *(ull*)(d0 + base) = p0;
    *(ull*)(d1 + base) = p1;
}

__global__ void __launch_bounds__(256) k_conv_x(const float* __restrict__ s)  { conv_body2(s, (char*)g_xt0, (char*)g_xt1); }
__global__ void __launch_bounds__(256) k_conv_w1(const float* __restrict__ s) { conv_body2(s, (char*)g_w1t0, (char*)g_w1t1); }

// ---------------- HMMA bf16 2-term GEMM for z -------------------------------
// z[128*by + m, 128*bx + n] = (x0+x1)(w0+w1)^T via products 00, 01, 10.
__global__ void __launch_bounds__(256, 1) k_mm_z() {
    extern __shared__ char smem[];
    uint32_t sb = (s2u(smem) + 127u) & ~127u;
    const int NT = 4;
    const uint32_t STAGE = (uint32_t)NT * TILEB;

    int tid = threadIdx.x, lane = tid & 31, wid = tid >> 5;
    int wm = wid & 1, wn = wid >> 1;
    int bx = blockIdx.x, by = blockIdx.y;

    const ull* As[2] = {g_xt0, g_xt1};
    const ull* Bs[2] = {g_w1t0, g_w1t1};
    const int PA[3] = {0, 0, 1};
    const int PB[3] = {0, 1, 0};

    uint32_t rowA[4];
    {
        int ra = wm * 64 + (lane & 15);
        #pragma unroll
        for (int mt = 0; mt < 4; mt++) {
            int rr = ra + mt * 16;
            rowA[mt] = (uint32_t)(rr * 128 + ((rr & 7) << 4));
        }
    }
    uint32_t acol = (uint32_t)((lane >> 4) * 16);
    uint32_t rowB[2];
    {
        int rb = wn * 32 + ((lane >> 4) << 3) + (lane & 7);
        #pragma unroll
        for (int n2 = 0; n2 < 2; n2++) {
            int rr = rb + n2 * 16;
            rowB[n2] = (uint32_t)(rr * 128 + ((rr & 7) << 4));
        }
    }
    uint32_t bcol = (uint32_t)(((lane >> 3) & 1) * 16);

    float acc[64];
    #pragma unroll
    for (int i = 0; i < 64; i++) acc[i] = 0.f;

    auto issue = [&](int kc, int s) {
        uint32_t dst = sb + (uint32_t)s * STAGE;
        #pragma unroll
        for (int t = 0; t < 2; t++) {
            const char* src = (const char*)As[t] + ((size_t)by * NCHUNK + kc) * TILEB;
            #pragma unroll
            for (int j = 0; j < 4; j++) {
                uint32_t o = (uint32_t)(tid + j * 256) * 16;
                cp16(dst + (uint32_t)t * TILEB + o, src + o);
            }
        }
        #pragma unroll
        for (int t = 0; t < 2; t++) {
            const char* src = (const char*)Bs[t] + ((size_t)bx * NCHUNK + kc) * TILEB;
            #pragma unroll
            for (int j = 0; j < 4; j++) {
                uint32_t o = (uint32_t)(tid + j * 256) * 16;
                cp16(dst + (uint32_t)(2 + t) * TILEB + o, src + o);
            }
        }
        cp_commit();
    };

    issue(0, 0);
    issue(1, 1);

    for (int kc = 0; kc < NCHUNK; kc++) {
        int s = kc & 1;
        if (kc == NCHUNK - 1) cp_wait<0>(); else cp_wait<1>();
        __syncthreads();
        uint32_t stg = sb + (uint32_t)s * STAGE;
        #pragma unroll
        for (int p = 0; p < 3; p++) {
            uint32_t Ab = stg + (uint32_t)PA[p] * TILEB;
            uint32_t Bb = stg + (uint32_t)(2 + PB[p]) * TILEB;
            #pragma unroll
            for (int ks = 0; ks < 4; ks++) {
                uint32_t ka = (uint32_t)(ks * 32) + acol;
                uint32_t kb = (uint32_t)(ks * 32) + bcol;
                uint32_t bf[2][4], af[4][4];
                ldsm4(bf[0], (Bb + rowB[0]) ^ kb);
                ldsm4(bf[1], (Bb + rowB[1]) ^ kb);
                #pragma unroll
                for (int mt = 0; mt < 4; mt++)
                    ldsm4(af[mt], (Ab + rowA[mt]) ^ ka);
                #pragma unroll
                for (int mt = 0; mt < 4; mt++) {
                    #pragma unroll
                    for (int nt = 0; nt < 4; nt++)
                        mma16816(&acc[(mt * 4 + nt) * 4], af[mt],
                                 &bf[nt >> 1][(nt & 1) * 2]);
                }
            }
        }
        __syncthreads();
        if (kc + 2 < NCHUNK) issue(kc + 2, s);
    }

    int rbase = by * 128 + wm * 64 + (lane >> 2);
    int cbase = bx * 128 + wn * 32 + (lane & 3) * 2;
    #pragma unroll
    for (int mt = 0; mt < 4; mt++) {
        #pragma unroll
        for (int nt = 0; nt < 4; nt++) {
            const float* a4 = &acc[(mt * 4 + nt) * 4];
            int row = rbase + mt * 16;
            int col = cbase + nt * 8;
            *(float2*)(g_z + (size_t)row * DFF + col)       = make_float2(a4[0], a4[1]);
            *(float2*)(g_z + (size_t)(row + 8) * DFF + col) = make_float2(a4[2], a4[3]);
        }
    }
}

// ---------------- transpose W2 [DM,DFF] -> g_w2t [DFF,DM] -------------------
__global__ void k_transpose(const float* __restrict__ W2) {
    __shared__ float tile[32][33];
    int x = blockIdx.x * 32 + threadIdx.x;
    int y0 = blockIdx.y * 32;
    for (int j = threadIdx.y; j < 32; j += 8)
        tile[j][threadIdx.x] = W2[(size_t)(y0 + j) * DFF + x];
    __syncthreads();
    int ox  = blockIdx.y * 32 + threadIdx.x;
    int oy0 = blockIdx.x * 32;
    for (int j = threadIdx.y; j < 32; j += 8)
        g_w2t[(size_t)(oy0 + j) * DM + ox] = tile[threadIdx.x][j];
}

// ---------------- exact top-256 radix select per token (verbatim R1) --------
__global__ void __launch_bounds__(256) k_topk() {
    __shared__ unsigned int keys[4096];
    __shared__ int hist[256];
    __shared__ int scan[256];
    __shared__ int sh_bin, sh_rem, sh_cnt, sh_eqbase;
    __shared__ int sel[256];
    __shared__ int warp_tot[8];

    int t = blockIdx.x, tid = threadIdx.x;
    const float* srow = g_scores + (size_t)t * DFF;

    for (int i = tid; i < 4096; i += 256) {
        unsigned int u = __float_as_uint(srow[i]);
        u = (u & 0x80000000u) ? ~u : (u | 0x80000000u);
        keys[i] = u;
    }
    unsigned int prefix = 0, pmask = 0;
    int remaining = KSEL;
    for (int pass = 0; pass < 4; pass++) {
        int shift = 24 - 8 * pass;
        hist[tid] = 0;
        __syncthreads();
        for (int i = tid; i < 4096; i += 256) {
            unsigned int k = keys[i];
            if ((k & pmask) == prefix) atomicAdd(&hist[(k >> shift) & 0xFF], 1);
        }
        __syncthreads();
        scan[tid] = hist[255 - tid];
        __syncthreads();
        #pragma unroll
        for (int off = 1; off < 256; off <<= 1) {
            int v = scan[tid];
            int add = (tid >= off) ? scan[tid - off] : 0;
            __syncthreads();
            scan[tid] = v + add;
            __syncthreads();
        }
        {
            int b = 255 - tid;
            int incl = scan[tid];
            int h = hist[b];
            int excl = incl - h;
            if (incl >= remaining && excl < remaining) {
                sh_bin = b;
                sh_rem = remaining - excl;
            }
        }
        __syncthreads();
        prefix |= ((unsigned)sh_bin) << shift;
        pmask  |= 0xFFu << shift;
        remaining = sh_rem;
        __syncthreads();
    }
    unsigned int thresh = prefix;

    if (tid == 0) sh_cnt = 0;
    __syncthreads();
    for (int i = tid; i < 4096; i += 256) {
        if (keys[i] > thresh) {
            int p = atomicAdd(&sh_cnt, 1);
            sel[p] = i;
        }
    }
    __syncthreads();
    int n_gt = sh_cnt;
    int n_eq = KSEL - n_gt;

    if (tid == 0) sh_eqbase = 0;
    __syncthreads();
    int lane = tid & 31, w = tid >> 5;
    for (int c = 0; c < 16; c++) {
        if (sh_eqbase >= n_eq) break;
        int i = c * 256 + tid;
        bool p = (keys[i] == thresh);
        unsigned int ball = __ballot_sync(0xffffffffu, p);
        int rin = __popc(ball & ((1u << lane) - 1));
        if (lane == 0) warp_tot[w] = __popc(ball);
        __syncthreads();
        int pre = 0;
        for (int ww = 0; ww < w; ww++) pre += warp_tot[ww];
        int grank = sh_eqbase + pre + rin;
        if (p && grank < n_eq) sel[n_gt + grank] = i;
        __syncthreads();
        if (tid == 0) {
            int tot = 0;
            for (int ww = 0; ww < 8; ww++) tot += warp_tot[ww];
            sh_eqbase += tot;
        }
        __syncthreads();
    }

    int i = sel[tid];
    g_idx[(size_t)t * KSEL + tid] = i;
    float z = g_z[(size_t)t * DFF + i];
    g_asel[(size_t)t * KSEL + tid] = gelu_f(z);
}

// ---------------- fused DeepSets per token (verbatim R1) --------------------
__global__ void __launch_bounds__(256) k_deepsets(
    const float* __restrict__ phi1_w, const float* __restrict__ phi1_b,
    const float* __restrict__ ln1w,   const float* __restrict__ ln1b,
    const float* __restrict__ phi2_w, const float* __restrict__ phi2_b,
    const float* __restrict__ ln2w,   const float* __restrict__ ln2b,
    const float* __restrict__ rho1_w, const float* __restrict__ rho1_b,
    const float* __restrict__ rho2_w, const float* __restrict__ rho2_b) {
    __shared__ float s_p1w[DH2], s_p1b[DH2], s_l1w[DH2], s_l1b[DH2];
    __shared__ float s_p2w[DH * DH2], s_p2b[DH], s_l2w[DH], s_l2b[DH];
    __shared__ float s_r1w[DR * DH], s_r1b[DR], s_r2w[DR];
    __shared__ float s_wsum[8][DH];
    __shared__ float s_ctx[DH];

    int t = blockIdx.x, tid = threadIdx.x;
    if (tid < DH2) {
        s_p1w[tid] = phi1_w[tid]; s_p1b[tid] = phi1_b[tid];
        s_l1w[tid] = ln1w[tid];   s_l1b[tid] = ln1b[tid];
    }
    if (tid < DH) {
        s_p2b[tid] = phi2_b[tid]; s_l2w[tid] = ln2w[tid]; s_l2b[tid] = ln2b[tid];
    }
    if (tid < DR) { s_r1b[tid] = rho1_b[tid]; s_r2w[tid] = rho2_w[tid]; }
    for (int i = tid; i < DH * DH2; i += 256) s_p2w[i] = phi2_w[i];
    for (int i = tid; i < DR * DH; i += 256) s_r1w[i] = rho1_w[i];
    float r2b = rho2_b[0];
    __syncthreads();

    float a = g_asel[(size_t)t * KSEL + tid];

    float e1[DH2];
    float mu = 0.f;
    #pragma unroll
    for (int j = 0; j < DH2; j++) { e1[j] = fmaf(a, s_p1w[j], s_p1b[j]); mu += e1[j]; }
    mu *= (1.0f / DH2);
    float var = 0.f;
    #pragma unroll
    for (int j = 0; j < DH2; j++) { float d = e1[j] - mu; var += d * d; }
    float inv = rsqrtf(var * (1.0f / DH2) + 1e-5f);
    #pragma unroll
    for (int j = 0; j < DH2; j++)
        e1[j] = gelu_f((e1[j] - mu) * inv * s_l1w[j] + s_l1b[j]);

    float e2[DH];
    #pragma unroll 4
    for (int h = 0; h < DH; h++) {
        float a0 = 0.f, a1 = 0.f, a2 = 0.f, a3 = 0.f;
        const float* wr = &s_p2w[h * DH2];
        #pragma unroll
        for (int j = 0; j < DH2; j += 4) {
            float4 w4 = *(const float4*)(wr + j);
            a0 = fmaf(e1[j + 0], w4.x, a0);
            a1 = fmaf(e1[j + 1], w4.y, a1);
            a2 = fmaf(e1[j + 2], w4.z, a2);
            a3 = fmaf(e1[j + 3], w4.w, a3);
        }
        e2[h] = ((a0 + a1) + (a2 + a3)) + s_p2b[h];
    }
    float mu2 = 0.f;
    #pragma unroll
    for (int h = 0; h < DH; h++) mu2 += e2[h];
    mu2 *= (1.0f / DH);
    float var2 = 0.f;
    #pragma unroll
    for (int h = 0; h < DH; h++) { float d = e2[h] - mu2; var2 += d * d; }
    float inv2 = rsqrtf(var2 * (1.0f / DH) + 1e-5f);
    #pragma unroll
    for (int h = 0; h < DH; h++)
        e2[h] = (e2[h] - mu2) * inv2 * s_l2w[h] + s_l2b[h];

    int lane = tid & 31, w = tid >> 5;
    #pragma unroll
    for (int h = 0; h < DH; h++) {
        float v = e2[h];
        v += __shfl_down_sync(0xffffffffu, v, 16);
        v += __shfl_down_sync(0xffffffffu, v, 8);
        v += __shfl_down_sync(0xffffffffu, v, 4);
        v += __shfl_down_sync(0xffffffffu, v, 2);
        v += __shfl_down_sync(0xffffffffu, v, 1);
        if (lane == 0) s_wsum[w][h] = v;
    }
    __syncthreads();
    if (tid < DH) {
        float s = 0.f;
        #pragma unroll
        for (int ww = 0; ww < 8; ww++) s += s_wsum[ww][tid];
        s_ctx[tid] = s * (1.0f / KSEL);
    }
    __syncthreads();
    #pragma unroll
    for (int h = 0; h < DH; h++) e2[h] += s_ctx[h];

    float man = r2b;
    #pragma unroll 2
    for (int m = 0; m < DR; m++) {
        float a0 = 0.f, a1 = 0.f, a2 = 0.f, a3 = 0.f;
        const float* wr = &s_r1w[m * DH];
        #pragma unroll
        for (int h = 0; h < DH; h += 4) {
            float4 w4 = *(const float4*)(wr + h);
            a0 = fmaf(e2[h + 0], w4.x, a0);
            a1 = fmaf(e2[h + 1], w4.y, a1);
            a2 = fmaf(e2[h + 2], w4.z, a2);
            a3 = fmaf(e2[h + 3], w4.w, a3);
        }
        float acc = ((a0 + a1) + (a2 + a3)) + s_r1b[m];
        man = fmaf(s_r2w[m], gelu_f(acc), man);
    }
    g_man[(size_t)t * KSEL + tid] = man;
}

// ---------------- out[t,:] = sum_k man[t,k] * W2T[idx[t,k], :] --------------
__global__ void __launch_bounds__(256) k_out(float* __restrict__ out) {
    __shared__ float s_man[KSEL];
    __shared__ int s_idx[KSEL];
    int t = blockIdx.x, tid = threadIdx.x;
    s_man[tid] = g_man[(size_t)t * KSEL + tid];
    s_idx[tid] = g_idx[(size_t)t * KSEL + tid];
    __syncthreads();
    float4 acc = make_float4(0.f, 0.f, 0.f, 0.f);
    #pragma unroll 8
    for (int k = 0; k < KSEL; k++) {
        float m = s_man[k];
        float4 wv = ((const float4*)(g_w2t + (size_t)s_idx[k] * DM))[tid];
        acc.x = fmaf(m, wv.x, acc.x);
        acc.y = fmaf(m, wv.y, acc.y);
        acc.z = fmaf(m, wv.z, acc.z);
        acc.w = fmaf(m, wv.w, acc.w);
    }
    ((float4*)(out + (size_t)t * DM))[tid] = acc;
}

// ---------------- launch ----------------------------------------------------
extern "C" void kernel_launch(void* const* d_in, const int* in_sizes, int n_in,
                              void* d_out, int out_size) {
    const float* x      = (const float*)d_in[0];
    const float* W1     = (const float*)d_in[1];
    const float* W2     = (const float*)d_in[2];
    const float* Wr1    = (const float*)d_in[3];
    const float* Wr2    = (const float*)d_in[4];
    const float* ln_w   = (const float*)d_in[5];
    const float* ln_b   = (const float*)d_in[6];
    const float* phi1_w = (const float*)d_in[7];
    const float* phi1_b = (const float*)d_in[8];
    const float* pl1w   = (const float*)d_in[9];
    const float* pl1b   = (const float*)d_in[10];
    const float* phi2_w = (const float*)d_in[11];
    const float* phi2_b = (const float*)d_in[12];
    const float* pl2w   = (const float*)d_in[13];
    const float* pl2b   = (const float*)d_in[14];
    const float* rho1_w = (const float*)d_in[15];
    const float* rho1_b = (const float*)d_in[16];
    const float* rho2_w = (const float*)d_in[17];
    const float* rho2_b = (const float*)d_in[18];
    float* out = (float*)d_out;

    const int smem4 = 256 + 4 * 2 * TILEB;  // 131328
    cudaFuncSetAttribute(k_mm_z, cudaFuncAttributeMaxDynamicSharedMemorySize, smem4);

    // z path (precision-insensitive): bf16 2-term HMMA
    k_conv_x<<<T_TOK, 256>>>(x);
    k_conv_w1<<<DFF, 256>>>(W1);
    k_mm_z<<<dim3(DFF / 128, T_TOK / 128), 256, smem4>>>();

    // router chain (top-k-sensitive): byte-identical R1 fp32 path
    k_ln<<<T_TOK, 256>>>(x, ln_w, ln_b);
    k_gemm_router1<<<dim3(DM / 128, T_TOK / 128), 256>>>(Wr1);
    k_gemm_scores<<<dim3(DFF / 128, T_TOK / 128), 256>>>(Wr2);

    k_transpose<<<dim3(DFF / 32, DM / 32), dim3(32, 8)>>>(W2);
    k_topk<<<T_TOK, 256>>>();
    k_deepsets<<<T_TOK, 256>>>(phi1_w, phi1_b, pl1w, pl1b,
                               phi2_w, phi2_b, pl2w, pl2b,
                               rho1_w, rho1_b, rho2_w, rho2_b);
    k_out<<<T_TOK, 256>>>(out);
}

// round 6
// speedup vs baseline: 1.4405x; 1.1536x over previous
#include <cuda_runtime.h>
#include <cuda_bf16.h>
#include <cstdint>

#define T_TOK 4096
#define DM    1024
#define DFF   4096
#define KSEL  256
#define DH    64
#define DH2   32
#define DR    128
#define TILEB 16384

typedef unsigned long long ull;

// ---------------- scratch (static device globals) ---------------------------
__device__ float g_xn[(size_t)T_TOK * DM];
__device__ float g_h[(size_t)T_TOK * DM];
__device__ float g_scores[(size_t)T_TOK * DFF];
__device__ float g_z[(size_t)T_TOK * DFF];
__device__ float g_asel[(size_t)T_TOK * KSEL];
__device__ float g_man[(size_t)T_TOK * KSEL];
__device__ int   g_idx[(size_t)T_TOK * KSEL];

// bf16 2-term split buffers (blocked + SW128-swizzled 128x64 tiles)
__device__ ull g_xt0[(size_t)T_TOK * DM / 4],  g_xt1[(size_t)T_TOK * DM / 4];
__device__ ull g_w1t0[(size_t)DFF * DM / 4],   g_w1t1[(size_t)DFF * DM / 4];
__device__ ull g_ht0[(size_t)T_TOK * DM / 4],  g_ht1[(size_t)T_TOK * DM / 4];
__device__ ull g_wr2t0[(size_t)DFF * DM / 4],  g_wr2t1[(size_t)DFF * DM / 4];
__device__ ull g_at0[(size_t)T_TOK * DFF / 4], g_at1[(size_t)T_TOK * DFF / 4];
__device__ ull g_w2t0[(size_t)DM * DFF / 4],   g_w2t1[(size_t)DM * DFF / 4];

// ---------------- helpers ---------------------------------------------------
__device__ __forceinline__ float gelu_f(float x) {
    return 0.5f * x * (1.0f + erff(x * 0.7071067811865475f));
}
__device__ __forceinline__ ull pack2(float lo, float hi) {
    ull r; asm("mov.b64 %0, {%1,%2};" : "=l"(r) : "f"(lo), "f"(hi)); return r;
}
__device__ __forceinline__ void unpack2(ull v, float &lo, float &hi) {
    asm("mov.b64 {%0,%1}, %2;" : "=f"(lo), "=f"(hi) : "l"(v));
}
__device__ __forceinline__ ull ffma2(ull a, ull b, ull c) {
    ull d; asm("fma.rn.f32x2 %0, %1, %2, %3;" : "=l"(d) : "l"(a), "l"(b), "l"(c));
    return d;
}
__device__ __forceinline__ uint32_t s2u(const void* p) {
    uint32_t a;
    asm("{ .reg .u64 t; cvta.to.shared.u64 t, %1; cvt.u32.u64 %0, t; }" : "=r"(a) : "l"(p));
    return a;
}
__device__ __forceinline__ void cp16(uint32_t d, const void* s) {
    asm volatile("cp.async.cg.shared.global [%0], [%1], 16;" :: "r"(d), "l"(s) : "memory");
}
__device__ __forceinline__ void cp_commit() {
    asm volatile("cp.async.commit_group;" ::: "memory");
}
template <int N>
__device__ __forceinline__ void cp_wait() {
    asm volatile("cp.async.wait_group %0;" :: "n"(N) : "memory");
}
__device__ __forceinline__ void ldsm4(uint32_t* r, uint32_t addr) {
    asm volatile("ldmatrix.sync.aligned.m8n8.x4.shared.b16 {%0,%1,%2,%3}, [%4];"
                 : "=r"(r[0]), "=r"(r[1]), "=r"(r[2]), "=r"(r[3]) : "r"(addr));
}
__device__ __forceinline__ void mma16816(float* d, const uint32_t* a, const uint32_t* b) {
    asm volatile(
        "mma.sync.aligned.m16n8k16.row.col.f32.bf16.bf16.f32 "
        "{%0,%1,%2,%3}, {%4,%5,%6,%7}, {%8,%9}, {%0,%1,%2,%3};"
        : "+f"(d[0]), "+f"(d[1]), "+f"(d[2]), "+f"(d[3])
        : "r"(a[0]), "r"(a[1]), "r"(a[2]), "r"(a[3]), "r"(b[0]), "r"(b[1]));
}
__device__ __forceinline__ float key2f(unsigned int k) {
    unsigned int u = (k & 0x80000000u) ? (k & 0x7fffffffu) : ~k;
    return __uint_as_float(u);
}

// ---------------- layernorm of x -> g_xn (verbatim R1) ----------------------
__global__ void __launch_bounds__(256) k_ln(const float* __restrict__ x,
                                            const float* __restrict__ w,
                                            const float* __restrict__ b) {
    __shared__ float red[8];
    int t = blockIdx.x, tid = threadIdx.x;
    const float4* row = (const float4*)(x + (size_t)t * DM);
    float4 v = row[tid];
    float s = v.x + v.y + v.z + v.w;
    #pragma unroll
    for (int o = 16; o; o >>= 1) s += __shfl_down_sync(0xffffffffu, s, o);
    if ((tid & 31) == 0) red[tid >> 5] = s;
    __syncthreads();
    float tot = 0.f;
    #pragma unroll
    for (int i = 0; i < 8; i++) tot += red[i];
    float mu = tot * (1.0f / DM);
    __syncthreads();
    float dx = v.x - mu, dy = v.y - mu, dz = v.z - mu, dw = v.w - mu;
    float q = dx * dx + dy * dy + dz * dz + dw * dw;
    #pragma unroll
    for (int o = 16; o; o >>= 1) q += __shfl_down_sync(0xffffffffu, q, o);
    if ((tid & 31) == 0) red[tid >> 5] = q;
    __syncthreads();
    float vt = 0.f;
    #pragma unroll
    for (int i = 0; i < 8; i++) vt += red[i];
    float inv = rsqrtf(vt * (1.0f / DM) + 1e-5f);
    float4 wv = ((const float4*)w)[tid];
    float4 bv = ((const float4*)b)[tid];
    float4 o;
    o.x = dx * inv * wv.x + bv.x;
    o.y = dy * inv * wv.y + bv.y;
    o.z = dz * inv * wv.z + bv.z;
    o.w = dw * inv * wv.w + bv.w;
    ((float4*)(g_xn + (size_t)t * DM))[tid] = o;
}

// ---------------- fp32 FFMA2 GEMM core (verbatim R1 — bit-exact) ------------
__device__ __forceinline__ void gemm_core(const float* __restrict__ A,
                                          const float* __restrict__ B,
                                          float* __restrict__ C,
                                          int N, bool do_gelu) {
    const int K = 1024;
    __shared__ float As[8][128];
    __shared__ float Bs[8][128];
    int tid = threadIdx.x;
    int m0 = blockIdx.y * 128, n0 = blockIdx.x * 128;
    int lr = tid >> 1;
    int lc = (tid & 1) * 4;
    const float* Ag = A + (size_t)(m0 + lr) * K + lc;
    const float* Bg = B + (size_t)(n0 + lr) * K + lc;
    int tx = tid & 15, ty = tid >> 4;
    int mo = ty * 8, no = tx * 8;

    ull acc[32];
    #pragma unroll
    for (int i = 0; i < 32; i++) acc[i] = 0ull;

    float4 a4 = *(const float4*)Ag;
    float4 b4 = *(const float4*)Bg;

    #pragma unroll 1
    for (int kt = 0; kt < K / 8; kt++) {
        As[lc + 0][lr] = a4.x; As[lc + 1][lr] = a4.y;
        As[lc + 2][lr] = a4.z; As[lc + 3][lr] = a4.w;
        Bs[lc + 0][lr] = b4.x; Bs[lc + 1][lr] = b4.y;
        Bs[lc + 2][lr] = b4.z; Bs[lc + 3][lr] = b4.w;
        __syncthreads();
        if (kt + 1 < K / 8) {
            a4 = *(const float4*)(Ag + (kt + 1) * 8);
            b4 = *(const float4*)(Bg + (kt + 1) * 8);
        }
        #pragma unroll
        for (int k = 0; k < 8; k++) {
            float4 aA = *(const float4*)&As[k][mo];
            float4 aB = *(const float4*)&As[k][mo + 4];
            const ull* bp = (const ull*)&Bs[k][no];
            ull b0 = bp[0], b1 = bp[1], b2 = bp[2], b3 = bp[3];
            float am[8] = {aA.x, aA.y, aA.z, aA.w, aB.x, aB.y, aB.z, aB.w};
            #pragma unroll
            for (int i = 0; i < 8; i++) {
                ull ap = pack2(am[i], am[i]);
                acc[i * 4 + 0] = ffma2(ap, b0, acc[i * 4 + 0]);
                acc[i * 4 + 1] = ffma2(ap, b1, acc[i * 4 + 1]);
                acc[i * 4 + 2] = ffma2(ap, b2, acc[i * 4 + 2]);
                acc[i * 4 + 3] = ffma2(ap, b3, acc[i * 4 + 3]);
            }
        }
        __syncthreads();
    }
    #pragma unroll
    for (int i = 0; i < 8; i++) {
        float* crow = C + (size_t)(m0 + mo + i) * N + n0 + no;
        #pragma unroll
        for (int p = 0; p < 4; p++) {
            float lo, hi;
            unpack2(acc[i * 4 + p], lo, hi);
            if (do_gelu) { lo = gelu_f(lo); hi = gelu_f(hi); }
            crow[2 * p]     = lo;
            crow[2 * p + 1] = hi;
        }
    }
}

__global__ void __launch_bounds__(256, 2) k_gemm_router1(const float* __restrict__ Wr1) {
    gemm_core(g_xn, Wr1, g_h, DM, true);
}

// ---------------- split fp32 -> 2 bf16 terms, blocked swizzled tiles --------
template <int WIDTH>
__device__ __forceinline__ void conv2w(const float* __restrict__ src,
                                       char* __restrict__ d0,
                                       char* __restrict__ d1) {
    int r = blockIdx.x, tid = threadIdx.x;
    int c0 = blockIdx.y * 1024 + tid * 4;
    float4 v = *(const float4*)(src + (size_t)r * WIDTH + c0);
    int kc = c0 >> 6, cl = c0 & 63;
    uint32_t off = (uint32_t)((r & 127) * 128 + cl * 2);
    off ^= (off >> 3) & 0x70;
    size_t base = ((size_t)((r >> 7) * (WIDTH / 64) + kc)) * TILEB + off;
    float f[4] = {v.x, v.y, v.z, v.w};
    unsigned short u0[4], u1[4];
    #pragma unroll
    for (int j = 0; j < 4; j++) {
        __nv_bfloat16 h0 = __float2bfloat16(f[j]);
        float r1 = f[j] - __bfloat162float(h0);
        u0[j] = __bfloat16_as_ushort(h0);
        u1[j] = __bfloat16_as_ushort(__float2bfloat16(r1));
    }
    ull p0 = (ull)u0[0] | ((ull)u0[1] << 16) | ((ull)u0[2] << 32) | ((ull)u0[3] << 48);
    ull p1 = (ull)u1[0] | ((ull)u1[1] << 16) | ((ull)u1[2] << 32) | ((ull)u1[3] << 48);
    *(ull*)(d0 + base) = p0;
    *(ull*)(d1 + base) = p1;
}

__global__ void __launch_bounds__(256) k_conv_x(const float* __restrict__ s)   { conv2w<DM>(s, (char*)g_xt0, (char*)g_xt1); }
__global__ void __launch_bounds__(256) k_conv_w1(const float* __restrict__ s)  { conv2w<DM>(s, (char*)g_w1t0, (char*)g_w1t1); }
__global__ void __launch_bounds__(256) k_conv_h()                              { conv2w<DM>(g_h, (char*)g_ht0, (char*)g_ht1); }
__global__ void __launch_bounds__(256) k_conv_wr2(const float* __restrict__ s) { conv2w<DM>(s, (char*)g_wr2t0, (char*)g_wr2t1); }
__global__ void __launch_bounds__(256) k_conv_w2(const float* __restrict__ s)  { conv2w<DFF>(s, (char*)g_w2t0, (char*)g_w2t1); }

// ---------------- unified HMMA bf16 2-term GEMM (3 products) ----------------
// C[128*by+m, 128*bx+n] = sum_p A_{PA[p]}[m,:] . B_{PB[p]}[n,:],  K = NCH*64
template <int NCH>
__device__ __forceinline__ void gemm2t(const ull* __restrict__ A0, const ull* __restrict__ A1,
                                       const ull* __restrict__ B0, const ull* __restrict__ B1,
                                       float* __restrict__ C, int ldc) {
    extern __shared__ char smem[];
    uint32_t sb = (s2u(smem) + 127u) & ~127u;
    const uint32_t STAGE = 4u * TILEB;

    int tid = threadIdx.x, lane = tid & 31, wid = tid >> 5;
    int wm = wid & 1, wn = wid >> 1;
    int bx = blockIdx.x, by = blockIdx.y;

    const ull* As[2] = {A0, A1};
    const ull* Bs[2] = {B0, B1};
    const int PA[3] = {0, 0, 1};
    const int PB[3] = {0, 1, 0};

    uint32_t rowA[4];
    {
        int ra = wm * 64 + (lane & 15);
        #pragma unroll
        for (int mt = 0; mt < 4; mt++) {
            int rr = ra + mt * 16;
            rowA[mt] = (uint32_t)(rr * 128 + ((rr & 7) << 4));
        }
    }
    uint32_t acol = (uint32_t)((lane >> 4) * 16);
    uint32_t rowB[2];
    {
        int rb = wn * 32 + ((lane >> 4) << 3) + (lane & 7);
        #pragma unroll
        for (int n2 = 0; n2 < 2; n2++) {
            int rr = rb + n2 * 16;
            rowB[n2] = (uint32_t)(rr * 128 + ((rr & 7) << 4));
        }
    }
    uint32_t bcol = (uint32_t)(((lane >> 3) & 1) * 16);

    float acc[64];
    #pragma unroll
    for (int i = 0; i < 64; i++) acc[i] = 0.f;

    auto issue = [&](int kc, int s) {
        uint32_t dst = sb + (uint32_t)s * STAGE;
        #pragma unroll
        for (int t = 0; t < 2; t++) {
            const char* src = (const char*)As[t] + ((size_t)by * NCH + kc) * TILEB;
            #pragma unroll
            for (int j = 0; j < 4; j++) {
                uint32_t o = (uint32_t)(tid + j * 256) * 16;
                cp16(dst + (uint32_t)t * TILEB + o, src + o);
            }
        }
        #pragma unroll
        for (int t = 0; t < 2; t++) {
            const char* src = (const char*)Bs[t] + ((size_t)bx * NCH + kc) * TILEB;
            #pragma unroll
            for (int j = 0; j < 4; j++) {
                uint32_t o = (uint32_t)(tid + j * 256) * 16;
                cp16(dst + (uint32_t)(2 + t) * TILEB + o, src + o);
            }
        }
        cp_commit();
    };

    issue(0, 0);
    issue(1, 1);

    for (int kc = 0; kc < NCH; kc++) {
        int s = kc & 1;
        if (kc == NCH - 1) cp_wait<0>(); else cp_wait<1>();
        __syncthreads();
        uint32_t stg = sb + (uint32_t)s * STAGE;
        #pragma unroll
        for (int p = 0; p < 3; p++) {
            uint32_t Ab = stg + (uint32_t)PA[p] * TILEB;
            uint32_t Bb = stg + (uint32_t)(2 + PB[p]) * TILEB;
            #pragma unroll
            for (int ks = 0; ks < 4; ks++) {
                uint32_t ka = (uint32_t)(ks * 32) + acol;
                uint32_t kb = (uint32_t)(ks * 32) + bcol;
                uint32_t bf[2][4], af[4][4];
                ldsm4(bf[0], (Bb + rowB[0]) ^ kb);
                ldsm4(bf[1], (Bb + rowB[1]) ^ kb);
                #pragma unroll
                for (int mt = 0; mt < 4; mt++)
                    ldsm4(af[mt], (Ab + rowA[mt]) ^ ka);
                #pragma unroll
                for (int mt = 0; mt < 4; mt++) {
                    #pragma unroll
                    for (int nt = 0; nt < 4; nt++)
                        mma16816(&acc[(mt * 4 + nt) * 4], af[mt],
                                 &bf[nt >> 1][(nt & 1) * 2]);
                }
            }
        }
        __syncthreads();
        if (kc + 2 < NCH) issue(kc + 2, s);
    }

    int rbase = by * 128 + wm * 64 + (lane >> 2);
    int cbase = bx * 128 + wn * 32 + (lane & 3) * 2;
    #pragma unroll
    for (int mt = 0; mt < 4; mt++) {
        #pragma unroll
        for (int nt = 0; nt < 4; nt++) {
            const float* a4 = &acc[(mt * 4 + nt) * 4];
            int row = rbase + mt * 16;
            int col = cbase + nt * 8;
            *(float2*)(C + (size_t)row * ldc + col)       = make_float2(a4[0], a4[1]);
            *(float2*)(C + (size_t)(row + 8) * ldc + col) = make_float2(a4[2], a4[3]);
        }
    }
}

__global__ void __launch_bounds__(256, 1) k_mm_z() {
    gemm2t<16>(g_xt0, g_xt1, g_w1t0, g_w1t1, g_z, DFF);
}
__global__ void __launch_bounds__(256, 1) k_mm_scores() {
    gemm2t<16>(g_ht0, g_ht1, g_wr2t0, g_wr2t1, g_scores, DFF);
}
__global__ void __launch_bounds__(256, 1) k_mm_out(float* __restrict__ out) {
    gemm2t<64>(g_at0, g_at1, g_w2t0, g_w2t1, out, DM);
}

// ---------------- top-256: radix select on approx + exact fp32 rescue -------
__global__ void __launch_bounds__(256) k_topk(const float* __restrict__ Wr2) {
    __shared__ unsigned int keys[4096];
    __shared__ int hist[256];
    __shared__ int scan[256];
    __shared__ int sh_bin, sh_rem, sh_cnt, sh_nc;
    __shared__ int sel[256];
    __shared__ int cand[256];
    __shared__ float cand_s[256];

    int t = blockIdx.x, tid = threadIdx.x;
    const float* srow = g_scores + (size_t)t * DFF;

    for (int i = tid; i < 4096; i += 256) {
        unsigned int u = __float_as_uint(srow[i]);
        u = (u & 0x80000000u) ? ~u : (u | 0x80000000u);
        keys[i] = u;
    }
    unsigned int prefix = 0, pmask = 0;
    int remaining = KSEL;
    for (int pass = 0; pass < 4; pass++) {
        int shift = 24 - 8 * pass;
        hist[tid] = 0;
        __syncthreads();
        for (int i = tid; i < 4096; i += 256) {
            unsigned int k = keys[i];
            if ((k & pmask) == prefix) atomicAdd(&hist[(k >> shift) & 0xFF], 1);
        }
        __syncthreads();
        scan[tid] = hist[255 - tid];
        __syncthreads();
        #pragma unroll
        for (int off = 1; off < 256; off <<= 1) {
            int v = scan[tid];
            int add = (tid >= off) ? scan[tid - off] : 0;
            __syncthreads();
            scan[tid] = v + add;
            __syncthreads();
        }
        {
            int b = 255 - tid;
            int incl = scan[tid];
            int h = hist[b];
            int excl = incl - h;
            if (incl >= remaining && excl < remaining) {
                sh_bin = b;
                sh_rem = remaining - excl;
            }
        }
        __syncthreads();
        prefix |= ((unsigned)sh_bin) << shift;
        pmask  |= 0xFFu << shift;
        remaining = sh_rem;
        __syncthreads();
    }

    // ---- rescue: approx threshold +- margin; recompute boundary exactly ----
    const float MARG = 4e-4f;   // >= 2x hard bound on |approx - exact| score
    float ts = key2f(prefix);
    float hi = ts + MARG, lo = ts - MARG;

    if (tid == 0) { sh_cnt = 0; sh_nc = 0; }
    __syncthreads();
    for (int i = tid; i < 4096; i += 256) {
        float s = key2f(keys[i]);
        if (s > hi) {
            int p = atomicAdd(&sh_cnt, 1);
            sel[p] = i;
        } else if (s >= lo) {
            int p = atomicAdd(&sh_nc, 1);
            if (p < 256) cand[p] = i;
        }
    }
    __syncthreads();
    int n_in = sh_cnt;
    int ncand = min(sh_nc, 256);
    int need = KSEL - n_in;

    // exact sequential-fp32 scores for candidates (bit-identical to the FFMA
    // GEMM's per-element accumulation order, given identical fp32 g_h)
    const float* hr = g_h + (size_t)t * DM;
    for (int c = tid; c < ncand; c += 256) {
        const float* wr = Wr2 + (size_t)cand[c] * DM;
        float acc = 0.f;
        for (int k = 0; k < DM; k++) acc = fmaf(hr[k], wr[k], acc);
        cand_s[c] = acc;
    }
    __syncthreads();
    if (tid == 0) {
        for (int j = 0; j < need; j++) {
            int best = -1; float bs = 0.f;
            for (int c = 0; c < ncand; c++) {
                int ci = cand[c];
                if (ci < 0) continue;
                float s = cand_s[c];
                if (best < 0 || s > bs || (s == bs && ci < cand[best])) {
                    bs = s; best = c;
                }
            }
            sel[n_in + j] = cand[best];
            cand[best] = -1;
        }
    }
    __syncthreads();

    int i = sel[tid];
    g_idx[(size_t)t * KSEL + tid] = i;
    float z = g_z[(size_t)t * DFF + i];
    g_asel[(size_t)t * KSEL + tid] = gelu_f(z);
}

// ---------------- fused DeepSets per token (verbatim R1) --------------------
__global__ void __launch_bounds__(256) k_deepsets(
    const float* __restrict__ phi1_w, const float* __restrict__ phi1_b,
    const float* __restrict__ ln1w,   const float* __restrict__ ln1b,
    const float* __restrict__ phi2_w, const float* __restrict__ phi2_b,
    const float* __restrict__ ln2w,   const float* __restrict__ ln2b,
    const float* __restrict__ rho1_w, const float* __restrict__ rho1_b,
    const float* __restrict__ rho2_w, const float* __restrict__ rho2_b) {
    __shared__ float s_p1w[DH2], s_p1b[DH2], s_l1w[DH2], s_l1b[DH2];
    __shared__ float s_p2w[DH * DH2], s_p2b[DH], s_l2w[DH], s_l2b[DH];
    __shared__ float s_r1w[DR * DH], s_r1b[DR], s_r2w[DR];
    __shared__ float s_wsum[8][DH];
    __shared__ float s_ctx[DH];

    int t = blockIdx.x, tid = threadIdx.x;
    if (tid < DH2) {
        s_p1w[tid] = phi1_w[tid]; s_p1b[tid] = phi1_b[tid];
        s_l1w[tid] = ln1w[tid];   s_l1b[tid] = ln1b[tid];
    }
    if (tid < DH) {
        s_p2b[tid] = phi2_b[tid]; s_l2w[tid] = ln2w[tid]; s_l2b[tid] = ln2b[tid];
    }
    if (tid < DR) { s_r1b[tid] = rho1_b[tid]; s_r2w[tid] = rho2_w[tid]; }
    for (int i = tid; i < DH * DH2; i += 256) s_p2w[i] = phi2_w[i];
    for (int i = tid; i < DR * DH; i += 256) s_r1w[i] = rho1_w[i];
    float r2b = rho2_b[0];
    __syncthreads();

    float a = g_asel[(size_t)t * KSEL + tid];

    float e1[DH2];
    float mu = 0.f;
    #pragma unroll
    for (int j = 0; j < DH2; j++) { e1[j] = fmaf(a, s_p1w[j], s_p1b[j]); mu += e1[j]; }
    mu *= (1.0f / DH2);
    float var = 0.f;
    #pragma unroll
    for (int j = 0; j < DH2; j++) { float d = e1[j] - mu; var += d * d; }
    float inv = rsqrtf(var * (1.0f / DH2) + 1e-5f);
    #pragma unroll
    for (int j = 0; j < DH2; j++)
        e1[j] = gelu_f((e1[j] - mu) * inv * s_l1w[j] + s_l1b[j]);

    float e2[DH];
    #pragma unroll 4
    for (int h = 0; h < DH; h++) {
        float a0 = 0.f, a1 = 0.f, a2 = 0.f, a3 = 0.f;
        const float* wr = &s_p2w[h * DH2];
        #pragma unroll
        for (int j = 0; j < DH2; j += 4) {
            float4 w4 = *(const float4*)(wr + j);
            a0 = fmaf(e1[j + 0], w4.x, a0);
            a1 = fmaf(e1[j + 1], w4.y, a1);
            a2 = fmaf(e1[j + 2], w4.z, a2);
            a3 = fmaf(e1[j + 3], w4.w, a3);
        }
        e2[h] = ((a0 + a1) + (a2 + a3)) + s_p2b[h];
    }
    float mu2 = 0.f;
    #pragma unroll
    for (int h = 0; h < DH; h++) mu2 += e2[h];
    mu2 *= (1.0f / DH);
    float var2 = 0.f;
    #pragma unroll
    for (int h = 0; h < DH; h++) { float d = e2[h] - mu2; var2 += d * d; }
    float inv2 = rsqrtf(var2 * (1.0f / DH) + 1e-5f);
    #pragma unroll
    for (int h = 0; h < DH; h++)
        e2[h] = (e2[h] - mu2) * inv2 * s_l2w[h] + s_l2b[h];

    int lane = tid & 31, w = tid >> 5;
    #pragma unroll
    for (int h = 0; h < DH; h++) {
        float v = e2[h];
        v += __shfl_down_sync(0xffffffffu, v, 16);
        v += __shfl_down_sync(0xffffffffu, v, 8);
        v += __shfl_down_sync(0xffffffffu, v, 4);
        v += __shfl_down_sync(0xffffffffu, v, 2);
        v += __shfl_down_sync(0xffffffffu, v, 1);
        if (lane == 0) s_wsum[w][h] = v;
    }
    __syncthreads();
    if (tid < DH) {
        float s = 0.f;
        #pragma unroll
        for (int ww = 0; ww < 8; ww++) s += s_wsum[ww][tid];
        s_ctx[tid] = s * (1.0f / KSEL);
    }
    __syncthreads();
    #pragma unroll
    for (int h = 0; h < DH; h++) e2[h] += s_ctx[h];

    float man = r2b;
    #pragma unroll 2
    for (int m = 0; m < DR; m++) {
        float a0 = 0.f, a1 = 0.f, a2 = 0.f, a3 = 0.f;
        const float* wr = &s_r1w[m * DH];
        #pragma unroll
        for (int h = 0; h < DH; h += 4) {
            float4 w4 = *(const float4*)(wr + h);
            a0 = fmaf(e2[h + 0], w4.x, a0);
            a1 = fmaf(e2[h + 1], w4.y, a1);
            a2 = fmaf(e2[h + 2], w4.z, a2);
            a3 = fmaf(e2[h + 3], w4.w, a3);
        }
        float acc = ((a0 + a1) + (a2 + a3)) + s_r1b[m];
        man = fmaf(s_r2w[m], gelu_f(acc), man);
    }
    g_man[(size_t)t * KSEL + tid] = man;
}

// ---------------- a_man dense 2-term build: zero + scatter ------------------
__global__ void __launch_bounds__(256) k_zero_at() {
    size_t i0 = ((size_t)blockIdx.x * 256 + threadIdx.x) * 4;
    #pragma unroll
    for (int j = 0; j < 4; j++) { g_at0[i0 + j] = 0ull; g_at1[i0 + j] = 0ull; }
}

__global__ void __launch_bounds__(256) k_scatter() {
    int t = blockIdx.x, tid = threadIdx.x;
    int i = g_idx[(size_t)t * KSEL + tid];
    float m = g_man[(size_t)t * KSEL + tid];
    __nv_bfloat16 m0 = __float2bfloat16(m);
    __nv_bfloat16 m1 = __float2bfloat16(m - __bfloat162float(m0));
    int kc = i >> 6, cl = i & 63;
    uint32_t off = (uint32_t)((t & 127) * 128 + cl * 2);
    off ^= (off >> 3) & 0x70;
    size_t base = ((size_t)((t >> 7) * (DFF / 64) + kc)) * TILEB + off;
    *(unsigned short*)((char*)g_at0 + base) = __bfloat16_as_ushort(m0);
    *(unsigned short*)((char*)g_at1 + base) = __bfloat16_as_ushort(m1);
}

// ---------------- launch ----------------------------------------------------
extern "C" void kernel_launch(void* const* d_in, const int* in_sizes, int n_in,
                              void* d_out, int out_size) {
    const float* x      = (const float*)d_in[0];
    const float* W1     = (const float*)d_in[1];
    const float* W2     = (const float*)d_in[2];
    const float* Wr1    = (const float*)d_in[3];
    const float* Wr2    = (const float*)d_in[4];
    const float* ln_w   = (const float*)d_in[5];
    const float* ln_b   = (const float*)d_in[6];
    const float* phi1_w = (const float*)d_in[7];
    const float* phi1_b = (const float*)d_in[8];
    const float* pl1w   = (const float*)d_in[9];
    const float* pl1b   = (const float*)d_in[10];
    const float* phi2_w = (const float*)d_in[11];
    const float* phi2_b = (const float*)d_in[12];
    const float* pl2w   = (const float*)d_in[13];
    const float* pl2b   = (const float*)d_in[14];
    const float* rho1_w = (const float*)d_in[15];
    const float* rho1_b = (const float*)d_in[16];
    const float* rho2_w = (const float*)d_in[17];
    const float* rho2_b = (const float*)d_in[18];
    float* out = (float*)d_out;

    const int smem4 = 256 + 4 * 2 * TILEB;  // 131328
    cudaFuncSetAttribute(k_mm_z,      cudaFuncAttributeMaxDynamicSharedMemorySize, smem4);
    cudaFuncSetAttribute(k_mm_scores, cudaFuncAttributeMaxDynamicSharedMemorySize, smem4);
    cudaFuncSetAttribute(k_mm_out,    cudaFuncAttributeMaxDynamicSharedMemorySize, smem4);

    // z path (precision-insensitive): bf16 2-term HMMA
    k_conv_x<<<T_TOK, 256>>>(x);
    k_conv_w1<<<DFF, 256>>>(W1);
    k_mm_z<<<dim3(DFF / 128, T_TOK / 128), 256, smem4>>>();

    // router chain: h in exact fp32 (FFMA), scores approx HMMA + rescue
    k_ln<<<T_TOK, 256>>>(x, ln_w, ln_b);
    k_gemm_router1<<<dim3(DM / 128, T_TOK / 128), 256>>>(Wr1);
    k_conv_h<<<T_TOK, 256>>>();
    k_conv_wr2<<<DFF, 256>>>(Wr2);
    k_mm_scores<<<dim3(DFF / 128, T_TOK / 128), 256, smem4>>>();
    k_topk<<<T_TOK, 256>>>(Wr2);

    k_deepsets<<<T_TOK, 256>>>(phi1_w, phi1_b, pl1w, pl1b,
                               phi2_w, phi2_b, pl2w, pl2b,
                               rho1_w, rho1_b, rho2_w, rho2_b);

    // out = a_man @ W2^T as dense 2-term HMMA
    k_zero_at<<<(int)(((size_t)T_TOK * DFF / 4) / (256 * 4)), 256>>>();
    k_conv_w2<<<dim3(DM, DFF / 1024), 256>>>(W2);
    k_scatter<<<T_TOK, 256>>>();
    k_mm_out<<<dim3(DM / 128, T_TOK / 128), 256, smem4>>>(out);
}